// round 1
// baseline (speedup 1.0000x reference)
#include <cuda_runtime.h>
#include <math.h>

#define B_ 4096
#define F_ 16
#define H_ 1280
#define N_ 8
#define R_ 64
#define C_ (F_*H_)   // 20480
#define GB 8         // batches per LoRA CTA

// ---------------- device scratch (no allocations allowed) ----------------
__device__ float g_dot[B_*N_];
__device__ float g_xsq[B_];
__device__ float g_gwinv[N_];
__device__ int   g_expert[B_];
__device__ int   g_cnt[N_];
__device__ int   g_off[N_+1];
__device__ int   g_cur[N_];
__device__ int   g_perm[B_];

// ---------------- K0: gate_w row inverse-norms + reset counters ----------------
__global__ void k0_prep(const float* __restrict__ gw) {
    int tid = threadIdx.x;
    if (tid < N_) g_cnt[tid] = 0;
    int w = tid >> 5, lane = tid & 31;
    if (w < N_) {
        float s = 0.f;
        const float* row = gw + (size_t)w * C_;
        for (int i = lane; i < C_; i += 32) { float v = row[i]; s += v * v; }
        #pragma unroll
        for (int o = 16; o; o >>= 1) s += __shfl_xor_sync(0xffffffffu, s, o);
        if (lane == 0) g_gwinv[w] = 1.f / fmaxf(sqrtf(s), 1e-12f);
    }
}

// ---------------- K1: dots[b][n] = xf[b] . gate_w[n], plus ||xf||^2 ----------------
// CTA = 32 batches, 8 warps; warp w owns batches 4w..4w+3 x all 8 experts.
__global__ __launch_bounds__(256) void k1_dots(const float* __restrict__ x,
                                               const float* __restrict__ gw) {
    __shared__ float xs[32 * 256];
    __shared__ float gws[8 * 256];
    int tid = threadIdx.x;
    int warp = tid >> 5, lane = tid & 31;
    int b0 = blockIdx.x * 32;

    float acc[4][8];
    float sq[4];
    #pragma unroll
    for (int i = 0; i < 4; i++) { sq[i] = 0.f;
        #pragma unroll
        for (int n = 0; n < 8; n++) acc[i][n] = 0.f; }

    const float4* x4g  = (const float4*)x;
    const float4* gw4g = (const float4*)gw;
    float4* xs4  = (float4*)xs;
    float4* gws4 = (float4*)gws;

    for (int ch = 0; ch < C_/256; ch++) {
        int c4 = ch * 64;
        #pragma unroll
        for (int j = 0; j < 2; j++) {
            int i4 = tid + 256*j; int n = i4 >> 6, col = i4 & 63;
            gws4[i4] = gw4g[(size_t)n * (C_/4) + c4 + col];
        }
        #pragma unroll
        for (int j = 0; j < 8; j++) {
            int i4 = tid + 256*j; int b = i4 >> 6, col = i4 & 63;
            xs4[i4] = x4g[(size_t)(b0 + b) * (C_/4) + c4 + col];
        }
        __syncthreads();
        #pragma unroll
        for (int k = 0; k < 2; k++) {
            int fc = k*32 + lane;
            float4 gv[8];
            #pragma unroll
            for (int n = 0; n < 8; n++) gv[n] = gws4[n*64 + fc];
            #pragma unroll
            for (int i = 0; i < 4; i++) {
                float4 xv = xs4[(4*warp + i)*64 + fc];
                sq[i] += xv.x*xv.x + xv.y*xv.y + xv.z*xv.z + xv.w*xv.w;
                #pragma unroll
                for (int n = 0; n < 8; n++)
                    acc[i][n] += xv.x*gv[n].x + xv.y*gv[n].y + xv.z*gv[n].z + xv.w*gv[n].w;
            }
        }
        __syncthreads();
    }
    #pragma unroll
    for (int i = 0; i < 4; i++) {
        float s = sq[i];
        #pragma unroll
        for (int o = 16; o; o >>= 1) s += __shfl_xor_sync(0xffffffffu, s, o);
        if (lane == 0) g_xsq[b0 + 4*warp + i] = s;
        #pragma unroll
        for (int n = 0; n < 8; n++) {
            float d = acc[i][n];
            #pragma unroll
            for (int o = 16; o; o >>= 1) d += __shfl_xor_sync(0xffffffffu, d, o);
            if (lane == 0) g_dot[(size_t)(b0 + 4*warp + i)*8 + n] = d;
        }
    }
}

// ---------------- K1b: logits + gumbel + argmax (first max, matches jnp.argmax) ----------------
__global__ void k1b_argmax(const float* __restrict__ u, const float* __restrict__ sigma_p) {
    int b = blockIdx.x * blockDim.x + threadIdx.x;
    if (b >= B_) return;
    float sigma = *sigma_p;
    float invx = 1.f / fmaxf(sqrtf(g_xsq[b]), 1e-12f);
    float best = -3.4e38f; int e = 0;
    #pragma unroll
    for (int n = 0; n < 8; n++) {
        float logit = sigma * g_dot[(size_t)b*8 + n] * invx * g_gwinv[n];
        float uu = u[(size_t)b*8 + n];
        float gmb = -logf(-logf(uu + 1e-12f) + 1e-12f);
        float z = logit + gmb;   // TAU = 1
        if (z > best) { best = z; e = n; }
    }
    g_expert[b] = e;
    atomicAdd(&g_cnt[e], 1);
}

// ---------------- K1c: tiny exclusive scan ----------------
__global__ void k1c_scan() {
    g_off[0] = 0;
    for (int n = 0; n < N_; n++) { g_off[n+1] = g_off[n] + g_cnt[n]; g_cur[n] = g_off[n]; }
}

// ---------------- K1d: scatter batch ids grouped by expert ----------------
__global__ void k1d_scatter() {
    int b = blockIdx.x * blockDim.x + threadIdx.x;
    if (b >= B_) return;
    int e = g_expert[b];
    int pos = atomicAdd(&g_cur[e], 1);
    g_perm[pos] = b;
}

// ---------------- K3: grouped LoRA. CTA = up to 8 same-expert batches ----------------
// phase 1: mid[128p][64r] = x @ down_w^T (H chunks of 32)
// phase 2: out[128p][64h-chunk] = mid @ up_w^T (20 chunks), staged via smem for coalesced stores
__global__ __launch_bounds__(256) void k3_lora(const float* __restrict__ x,
                                               const float* __restrict__ dw,
                                               const float* __restrict__ uw,
                                               float* __restrict__ out) {
    extern __shared__ float sm[];
    float* mid_s = sm;                       // 128*65  (aliases phase-1 tiles)
    float* xs    = sm;                       // 128*33
    float* dws   = sm + 128*33;              // 64*33
    float* up_s  = sm + 128*65;              // 64*65
    float* out_s = sm + 128*65 + 64*65;      // 128*65
    __shared__ int bs_sh[GB];
    __shared__ int info[2];

    int tid = threadIdx.x;
    if (tid == 0) {
        int rem = blockIdx.x; int e = -1, g = 0, start = 0;
        for (int n = 0; n < N_; n++) {
            int cnt = g_off[n+1] - g_off[n];
            int ng = (cnt + GB - 1) / GB;
            if (rem < ng) { e = n; start = g_off[n] + rem*GB;
                            g = g_off[n+1] - start; if (g > GB) g = GB; break; }
            rem -= ng;
        }
        info[0] = e; info[1] = g;
        if (e >= 0) for (int i = 0; i < GB; i++) {
            int ii = i < g ? i : g - 1;
            bs_sh[i] = g_perm[start + ii];
        }
    }
    __syncthreads();
    int e = info[0], g = info[1];
    if (e < 0) return;

    int pt  = tid & 31;   // lane: p-tile base (p = pt + 32*i, conflict-free)
    int grp = tid >> 5;   // warp: owns r (phase1) / h (phase2) sub-tile of 8

    const float4* x4g = (const float4*)x;
    const float4* dw4 = (const float4*)dw;
    const float4* uw4 = (const float4*)uw;

    float acc[4][8];
    #pragma unroll
    for (int i = 0; i < 4; i++)
        #pragma unroll
        for (int j = 0; j < 8; j++) acc[i][j] = 0.f;

    // ---- phase 1 ----
    for (int hc = 0; hc < H_/32; hc++) {
        int c4 = hc * 8;
        #pragma unroll
        for (int j = 0; j < 4; j++) {
            int i4 = tid + 256*j;
            int row = i4 >> 3, col = i4 & 7;
            int b = bs_sh[row >> 4], f = row & 15;
            float4 v = x4g[((size_t)b*F_ + f)*(H_/4) + c4 + col];
            float* d = &xs[row*33 + col*4];
            d[0]=v.x; d[1]=v.y; d[2]=v.z; d[3]=v.w;
        }
        #pragma unroll
        for (int j = 0; j < 2; j++) {
            int i4 = tid + 256*j;
            int row = i4 >> 3, col = i4 & 7;
            float4 v = dw4[((size_t)e*R_ + row)*(H_/4) + c4 + col];
            float* d = &dws[row*33 + col*4];
            d[0]=v.x; d[1]=v.y; d[2]=v.z; d[3]=v.w;
        }
        __syncthreads();
        #pragma unroll 4
        for (int c = 0; c < 32; c++) {
            float xv[4], wv[8];
            #pragma unroll
            for (int i = 0; i < 4; i++) xv[i] = xs[(pt + 32*i)*33 + c];
            #pragma unroll
            for (int j = 0; j < 8; j++) wv[j] = dws[(grp*8 + j)*33 + c];
            #pragma unroll
            for (int i = 0; i < 4; i++)
                #pragma unroll
                for (int j = 0; j < 8; j++) acc[i][j] += xv[i] * wv[j];
        }
        __syncthreads();
    }
    #pragma unroll
    for (int i = 0; i < 4; i++)
        #pragma unroll
        for (int j = 0; j < 8; j++)
            mid_s[(pt + 32*i)*65 + grp*8 + j] = acc[i][j];
    __syncthreads();

    // ---- phase 2 ----
    for (int hc = 0; hc < H_/64; hc++) {
        int h0 = hc * 64;
        #pragma unroll
        for (int j = 0; j < 4; j++) {
            int i4 = tid + 256*j;
            int row = i4 >> 4, col = i4 & 15;
            float4 v = uw4[((size_t)e*H_ + h0 + row)*(R_/4) + col];
            float* d = &up_s[row*65 + col*4];
            d[0]=v.x; d[1]=v.y; d[2]=v.z; d[3]=v.w;
        }
        __syncthreads();
        float a2[4][8];
        #pragma unroll
        for (int i = 0; i < 4; i++)
            #pragma unroll
            for (int j = 0; j < 8; j++) a2[i][j] = 0.f;
        #pragma unroll 4
        for (int r = 0; r < 64; r++) {
            float mv[4], uv[8];
            #pragma unroll
            for (int i = 0; i < 4; i++) mv[i] = mid_s[(pt + 32*i)*65 + r];
            #pragma unroll
            for (int j = 0; j < 8; j++) uv[j] = up_s[(grp*8 + j)*65 + r];
            #pragma unroll
            for (int i = 0; i < 4; i++)
                #pragma unroll
                for (int j = 0; j < 8; j++) a2[i][j] += mv[i] * uv[j];
        }
        #pragma unroll
        for (int i = 0; i < 4; i++)
            #pragma unroll
            for (int j = 0; j < 8; j++)
                out_s[(pt + 32*i)*65 + grp*8 + j] = a2[i][j];
        __syncthreads();
        #pragma unroll
        for (int j = 0; j < 8; j++) {
            int i4 = tid + 256*j;
            int row = i4 >> 4, col = i4 & 15;
            int gi = row >> 4;
            if (gi < g) {
                int b = bs_sh[gi], f = row & 15;
                const float* s = &out_s[row*65 + col*4];
                float4 v = make_float4(s[0], s[1], s[2], s[3]);
                ((float4*)out)[((size_t)b*F_ + f)*(H_/4) + (h0 >> 2) + col] = v;
            }
        }
        __syncthreads();
    }
}

// ---------------- launch ----------------
extern "C" void kernel_launch(void* const* d_in, const int* in_sizes, int n_in,
                              void* d_out, int out_size) {
    const float* x     = (const float*)d_in[0];
    const float* u     = (const float*)d_in[1];
    const float* gw    = (const float*)d_in[2];
    const float* sigma = (const float*)d_in[3];
    const float* dw    = (const float*)d_in[4];
    const float* uw    = (const float*)d_in[5];
    float* out = (float*)d_out;

    cudaFuncSetAttribute(k3_lora, cudaFuncAttributeMaxDynamicSharedMemorySize, 83200);

    k0_prep<<<1, 256>>>(gw);
    k1_dots<<<B_/32, 256>>>(x, gw);
    k1b_argmax<<<B_/256, 256>>>(u, sigma);
    k1c_scan<<<1, 1>>>();
    k1d_scatter<<<B_/256, 256>>>();
    k3_lora<<<B_/GB + N_, 256, 83200>>>(x, dw, uw, out);
}

// round 3
// speedup vs baseline: 2.3762x; 2.3762x over previous
#include <cuda_runtime.h>
#include <math.h>
#include <stdint.h>

#define B_ 4096
#define F_ 16
#define H_ 1280
#define N_ 8
#define R_ 64
#define C_ (F_*H_)   // 20480
#define GB 8         // batches per LoRA CTA

// ---------------- device scratch ----------------
__device__ float g_dot[B_*N_];
__device__ float g_xsq[B_];
__device__ float g_gwinv[N_];
__device__ int   g_expert[B_];
__device__ int   g_cnt[N_];
__device__ int   g_off[N_+1];
__device__ int   g_cur[N_];
__device__ int   g_perm[B_];

// ================= gating (passing since round 1) =================
__global__ void k0_prep(const float* __restrict__ gw) {
    int tid = threadIdx.x;
    if (tid < N_) g_cnt[tid] = 0;
    int w = tid >> 5, lane = tid & 31;
    if (w < N_) {
        float s = 0.f;
        const float* row = gw + (size_t)w * C_;
        for (int i = lane; i < C_; i += 32) { float v = row[i]; s += v * v; }
        #pragma unroll
        for (int o = 16; o; o >>= 1) s += __shfl_xor_sync(0xffffffffu, s, o);
        if (lane == 0) g_gwinv[w] = 1.f / fmaxf(sqrtf(s), 1e-12f);
    }
}

__global__ __launch_bounds__(256) void k1_dots(const float* __restrict__ x,
                                               const float* __restrict__ gw) {
    __shared__ float xs[32 * 256];
    __shared__ float gws[8 * 256];
    int tid = threadIdx.x;
    int warp = tid >> 5, lane = tid & 31;
    int b0 = blockIdx.x * 32;

    float acc[4][8];
    float sq[4];
    #pragma unroll
    for (int i = 0; i < 4; i++) { sq[i] = 0.f;
        #pragma unroll
        for (int n = 0; n < 8; n++) acc[i][n] = 0.f; }

    const float4* x4g  = (const float4*)x;
    const float4* gw4g = (const float4*)gw;
    float4* xs4  = (float4*)xs;
    float4* gws4 = (float4*)gws;

    for (int ch = 0; ch < C_/256; ch++) {
        int c4 = ch * 64;
        #pragma unroll
        for (int j = 0; j < 2; j++) {
            int i4 = tid + 256*j; int n = i4 >> 6, col = i4 & 63;
            gws4[i4] = gw4g[(size_t)n * (C_/4) + c4 + col];
        }
        #pragma unroll
        for (int j = 0; j < 8; j++) {
            int i4 = tid + 256*j; int b = i4 >> 6, col = i4 & 63;
            xs4[i4] = x4g[(size_t)(b0 + b) * (C_/4) + c4 + col];
        }
        __syncthreads();
        #pragma unroll
        for (int k = 0; k < 2; k++) {
            int fc = k*32 + lane;
            float4 gv[8];
            #pragma unroll
            for (int n = 0; n < 8; n++) gv[n] = gws4[n*64 + fc];
            #pragma unroll
            for (int i = 0; i < 4; i++) {
                float4 xv = xs4[(4*warp + i)*64 + fc];
                sq[i] += xv.x*xv.x + xv.y*xv.y + xv.z*xv.z + xv.w*xv.w;
                #pragma unroll
                for (int n = 0; n < 8; n++)
                    acc[i][n] += xv.x*gv[n].x + xv.y*gv[n].y + xv.z*gv[n].z + xv.w*gv[n].w;
            }
        }
        __syncthreads();
    }
    #pragma unroll
    for (int i = 0; i < 4; i++) {
        float s = sq[i];
        #pragma unroll
        for (int o = 16; o; o >>= 1) s += __shfl_xor_sync(0xffffffffu, s, o);
        if (lane == 0) g_xsq[b0 + 4*warp + i] = s;
        #pragma unroll
        for (int n = 0; n < 8; n++) {
            float d = acc[i][n];
            #pragma unroll
            for (int o = 16; o; o >>= 1) d += __shfl_xor_sync(0xffffffffu, d, o);
            if (lane == 0) g_dot[(size_t)(b0 + 4*warp + i)*8 + n] = d;
        }
    }
}

__global__ void k1b_argmax(const float* __restrict__ u, const float* __restrict__ sigma_p) {
    int b = blockIdx.x * blockDim.x + threadIdx.x;
    if (b >= B_) return;
    float sigma = *sigma_p;
    float invx = 1.f / fmaxf(sqrtf(g_xsq[b]), 1e-12f);
    float best = -3.4e38f; int e = 0;
    #pragma unroll
    for (int n = 0; n < 8; n++) {
        float logit = sigma * g_dot[(size_t)b*8 + n] * invx * g_gwinv[n];
        float uu = u[(size_t)b*8 + n];
        float gmb = -logf(-logf(uu + 1e-12f) + 1e-12f);
        float z = logit + gmb;
        if (z > best) { best = z; e = n; }
    }
    g_expert[b] = e;
    atomicAdd(&g_cnt[e], 1);
}

__global__ void k1c_scan() {
    g_off[0] = 0;
    for (int n = 0; n < N_; n++) { g_off[n+1] = g_off[n] + g_cnt[n]; g_cur[n] = g_off[n]; }
}

__global__ void k1d_scatter() {
    int b = blockIdx.x * blockDim.x + threadIdx.x;
    if (b >= B_) return;
    int e = g_expert[b];
    int pos = atomicAdd(&g_cur[e], 1);
    g_perm[pos] = b;
}

// ================= warp-mma helpers (base sm_103 target safe) =================
__device__ __forceinline__ uint32_t smem_u32(const void* p) {
    uint32_t a;
    asm("{ .reg .u64 t; cvta.to.shared.u64 t, %1; cvt.u32.u64 %0, t; }" : "=r"(a) : "l"(p));
    return a;
}
__device__ __forceinline__ void ldsm_x4(uint32_t* r, uint32_t addr) {
    asm volatile("ldmatrix.sync.aligned.m8n8.x4.shared.b16 {%0,%1,%2,%3}, [%4];"
                 : "=r"(r[0]), "=r"(r[1]), "=r"(r[2]), "=r"(r[3]) : "r"(addr));
}
__device__ __forceinline__ void mma_bf16(float* c, const uint32_t* a, const uint32_t* b) {
    asm volatile("mma.sync.aligned.m16n8k16.row.col.f32.bf16.bf16.f32 "
        "{%0,%1,%2,%3}, {%4,%5,%6,%7}, {%8,%9}, {%0,%1,%2,%3};"
        : "+f"(c[0]), "+f"(c[1]), "+f"(c[2]), "+f"(c[3])
        : "r"(a[0]), "r"(a[1]), "r"(a[2]), "r"(a[3]), "r"(b[0]), "r"(b[1]));
}
// pack two floats into bf16x2 word: low half = bf16(lo_arg), high half = bf16(hi_arg)
__device__ __forceinline__ uint32_t pk(float lo, float hi) {
    uint32_t r;
    asm("cvt.rn.satfinite.bf16x2.f32 %0, %1, %2;" : "=r"(r) : "f"(hi), "f"(lo));
    return r;
}
__device__ __forceinline__ void split2(float a, float b, uint32_t& h, uint32_t& l) {
    h = pk(a, b);
    float fa = __uint_as_float(h << 16);
    float fb = __uint_as_float(h & 0xFFFF0000u);
    l = pk(a - fa, b - fb);
}
__device__ __forceinline__ void st_hilo(char* hi_p, char* lo_p, float4 v) {
    uint32_t h0, l0, h1, l1;
    split2(v.x, v.y, h0, l0);
    split2(v.z, v.w, h1, l1);
    *(uint2*)hi_p = make_uint2(h0, h1);
    *(uint2*)lo_p = make_uint2(l0, l1);
}

// smem byte offsets; row stride 144B (72 halves) -> conflict-free ldmatrix
#define STRD 144
#define X_HI   0
#define X_LO   18432
#define W_HI   36864
#define W_LO   46080
#define MID_HI 0
#define MID_LO 18432
#define DYN_SMEM 55296

// ================= K3: warp-mma grouped LoRA =================
__global__ __launch_bounds__(256, 2)
void k3_mma(const float* __restrict__ x, const float* __restrict__ dw,
            const float* __restrict__ uw, float* __restrict__ out) {
    extern __shared__ char sm[];
    __shared__ int bs_sh[GB];
    __shared__ int info[2];

    int tid = threadIdx.x, wid = tid >> 5, lid = tid & 31;

    if (tid == 0) {
        int rem = blockIdx.x; int e = -1, g = 0, start = 0;
        for (int n = 0; n < N_; n++) {
            int cnt = g_off[n+1] - g_off[n];
            int ng = (cnt + GB - 1) / GB;
            if (rem < ng) { e = n; start = g_off[n] + rem*GB;
                            g = g_off[n+1] - start; if (g > GB) g = GB; break; }
            rem -= ng;
        }
        info[0] = e; info[1] = g;
        if (e >= 0) for (int i = 0; i < GB; i++) {
            int ii = i < g ? i : g - 1;
            bs_sh[i] = g_perm[start + ii];
        }
    }
    __syncthreads();
    int e = info[0], g = info[1];
    if (e < 0) return;

    uint32_t sb = smem_u32(sm);
    const float4* x4  = (const float4*)x;
    const float4* dw4 = (const float4*)dw;
    const float4* uw4 = (const float4*)uw;

    int ldr = tid >> 4;   // load row base (0..15)
    int ldc = tid & 15;   // float4 column (0..15) = 64 floats/row

    // ldmatrix lane address offsets (byte)
    uint32_t aoff = (uint32_t)((16*wid + (lid & 15))*STRD + (lid >> 4)*16);
    uint32_t boff = (uint32_t)(((lid & 7) + ((lid >> 4) & 1)*8)*STRD + ((lid >> 3) & 1)*16);

    // ---------------- phase 1: mid[128,64] = X[128,1280] @ DW[64,1280]^T ----------------
    float acc[8][4];
    #pragma unroll
    for (int i = 0; i < 8; i++)
        #pragma unroll
        for (int j = 0; j < 4; j++) acc[i][j] = 0.f;

    float4 xg[8], wg[4];
    // prologue: load chunk 0
    #pragma unroll
    for (int j = 0; j < 8; j++) {
        int row = ldr + 16*j;
        int bb = bs_sh[row >> 4], f = row & 15;
        xg[j] = x4[(size_t)(bb*16 + f)*320 + ldc];
    }
    #pragma unroll
    for (int j = 0; j < 4; j++) {
        int row = ldr + 16*j;
        wg[j] = dw4[(size_t)(e*64 + row)*320 + ldc];
    }
    #pragma unroll
    for (int j = 0; j < 8; j++) {
        int row = ldr + 16*j;
        st_hilo(sm + X_HI + row*STRD + ldc*8, sm + X_LO + row*STRD + ldc*8, xg[j]);
    }
    #pragma unroll
    for (int j = 0; j < 4; j++) {
        int row = ldr + 16*j;
        st_hilo(sm + W_HI + row*STRD + ldc*8, sm + W_LO + row*STRD + ldc*8, wg[j]);
    }
    __syncthreads();

    for (int ch = 0; ch < 20; ch++) {
        if (ch + 1 < 20) {
            #pragma unroll
            for (int j = 0; j < 8; j++) {
                int row = ldr + 16*j;
                int bb = bs_sh[row >> 4], f = row & 15;
                xg[j] = x4[(size_t)(bb*16 + f)*320 + (ch+1)*16 + ldc];
            }
            #pragma unroll
            for (int j = 0; j < 4; j++) {
                int row = ldr + 16*j;
                wg[j] = dw4[(size_t)(e*64 + row)*320 + (ch+1)*16 + ldc];
            }
        }
        // compute on chunk ch
        #pragma unroll
        for (int ks = 0; ks < 4; ks++) {
            uint32_t ah[4], al[4];
            ldsm_x4(ah, sb + X_HI + aoff + ks*32);
            ldsm_x4(al, sb + X_LO + aoff + ks*32);
            #pragma unroll
            for (int np = 0; np < 4; np++) {
                uint32_t bh[4], bl[4];
                ldsm_x4(bh, sb + W_HI + boff + np*16*STRD + ks*32);
                ldsm_x4(bl, sb + W_LO + boff + np*16*STRD + ks*32);
                mma_bf16(acc[2*np],   ah, bh);
                mma_bf16(acc[2*np],   ah, bl);
                mma_bf16(acc[2*np],   al, bh);
                mma_bf16(acc[2*np+1], ah, bh+2);
                mma_bf16(acc[2*np+1], ah, bl+2);
                mma_bf16(acc[2*np+1], al, bh+2);
            }
        }
        __syncthreads();
        if (ch + 1 < 20) {
            #pragma unroll
            for (int j = 0; j < 8; j++) {
                int row = ldr + 16*j;
                st_hilo(sm + X_HI + row*STRD + ldc*8, sm + X_LO + row*STRD + ldc*8, xg[j]);
            }
            #pragma unroll
            for (int j = 0; j < 4; j++) {
                int row = ldr + 16*j;
                st_hilo(sm + W_HI + row*STRD + ldc*8, sm + W_LO + row*STRD + ldc*8, wg[j]);
            }
            __syncthreads();
        }
    }

    // ---------------- mid -> smem bf16 hi/lo ----------------
    {
        int r0 = 16*wid + (lid >> 2);
        int co = (lid & 3)*4;  // byte offset of 2 halves within ntile
        #pragma unroll
        for (int nt = 0; nt < 8; nt++) {
            uint32_t h, l;
            split2(acc[nt][0], acc[nt][1], h, l);
            *(uint32_t*)(sm + MID_HI + r0*STRD + nt*16 + co) = h;
            *(uint32_t*)(sm + MID_LO + r0*STRD + nt*16 + co) = l;
            split2(acc[nt][2], acc[nt][3], h, l);
            *(uint32_t*)(sm + MID_HI + (r0+8)*STRD + nt*16 + co) = h;
            *(uint32_t*)(sm + MID_LO + (r0+8)*STRD + nt*16 + co) = l;
        }
    }
    __syncthreads();

    // resident A fragments for phase 2 (K = 64 -> 4 ksteps)
    uint32_t mah[4][4], mal[4][4];
    #pragma unroll
    for (int ks = 0; ks < 4; ks++) {
        ldsm_x4(mah[ks], sb + MID_HI + aoff + ks*32);
        ldsm_x4(mal[ks], sb + MID_LO + aoff + ks*32);
    }

    // ---------------- phase 2: out[128,1280] = mid[128,64] @ UW[1280,64]^T ----------------
    int bb_w = bs_sh[wid];
    float* outw = out + (size_t)(bb_w*16)*1280;

    // prologue: load UW chunk 0
    #pragma unroll
    for (int j = 0; j < 4; j++) {
        int row = ldr + 16*j;
        wg[j] = uw4[(size_t)(e*1280 + row)*16 + ldc];
    }
    #pragma unroll
    for (int j = 0; j < 4; j++) {
        int row = ldr + 16*j;
        st_hilo(sm + W_HI + row*STRD + ldc*8, sm + W_LO + row*STRD + ldc*8, wg[j]);
    }
    __syncthreads();

    for (int i = 0; i < 20; i++) {
        if (i + 1 < 20) {
            #pragma unroll
            for (int j = 0; j < 4; j++) {
                int row = ldr + 16*j;
                wg[j] = uw4[(size_t)(e*1280 + (i+1)*64 + row)*16 + ldc];
            }
        }
        float a2[8][4];
        #pragma unroll
        for (int p = 0; p < 8; p++)
            #pragma unroll
            for (int q = 0; q < 4; q++) a2[p][q] = 0.f;
        #pragma unroll
        for (int ks = 0; ks < 4; ks++) {
            #pragma unroll
            for (int np = 0; np < 4; np++) {
                uint32_t bh[4], bl[4];
                ldsm_x4(bh, sb + W_HI + boff + np*16*STRD + ks*32);
                ldsm_x4(bl, sb + W_LO + boff + np*16*STRD + ks*32);
                mma_bf16(a2[2*np],   mah[ks], bh);
                mma_bf16(a2[2*np],   mah[ks], bl);
                mma_bf16(a2[2*np],   mal[ks], bh);
                mma_bf16(a2[2*np+1], mah[ks], bh+2);
                mma_bf16(a2[2*np+1], mah[ks], bl+2);
                mma_bf16(a2[2*np+1], mal[ks], bh+2);
            }
        }
        // epilogue: direct 32B-sector stores
        if (wid < g) {
            int r0 = lid >> 2, c0 = (lid & 3)*2;
            #pragma unroll
            for (int nt = 0; nt < 8; nt++) {
                int col = i*64 + nt*8 + c0;
                *(float2*)(outw + (size_t)r0*1280 + col)     = make_float2(a2[nt][0], a2[nt][1]);
                *(float2*)(outw + (size_t)(r0+8)*1280 + col) = make_float2(a2[nt][2], a2[nt][3]);
            }
        }
        __syncthreads();
        if (i + 1 < 20) {
            #pragma unroll
            for (int j = 0; j < 4; j++) {
                int row = ldr + 16*j;
                st_hilo(sm + W_HI + row*STRD + ldc*8, sm + W_LO + row*STRD + ldc*8, wg[j]);
            }
            __syncthreads();
        }
    }
}

// ================= launch =================
extern "C" void kernel_launch(void* const* d_in, const int* in_sizes, int n_in,
                              void* d_out, int out_size) {
    const float* x     = (const float*)d_in[0];
    const float* u     = (const float*)d_in[1];
    const float* gw    = (const float*)d_in[2];
    const float* sigma = (const float*)d_in[3];
    const float* dw    = (const float*)d_in[4];
    const float* uw    = (const float*)d_in[5];
    float* out = (float*)d_out;

    cudaFuncSetAttribute(k3_mma, cudaFuncAttributeMaxDynamicSharedMemorySize, DYN_SMEM);

    k0_prep<<<1, 256>>>(gw);
    k1_dots<<<B_/32, 256>>>(x, gw);
    k1b_argmax<<<B_/256, 256>>>(u, sigma);
    k1c_scan<<<1, 1>>>();
    k1d_scatter<<<B_/256, 256>>>();
    k3_mma<<<B_/GB + N_, 256, DYN_SMEM>>>(x, dw, uw, out);
}